// round 7
// baseline (speedup 1.0000x reference)
#include <cuda_runtime.h>
#include <math.h>

#define N_NODES 100000
#define N_EDGES 3200000
#define IN_CH   128
#define HID     30
#define PAD     32
#define BUCKET  128            // max degree capacity (Poisson(32): overflow prob ~0)
#define NB_E4   3125           // (N_EDGES/4)/256
#define NB_XPROJ 12500         // N_NODES/8
#define ZROW    N_NODES        // index of the all-zero padding row
#define FULL    0xffffffffu

// ---- scratch (static device globals; no allocation anywhere) ----
__device__ int   d_cnt[N_NODES];
__device__ int   d_bucket[N_NODES * BUCKET];       // 51.2 MB
__device__ float d_bufA[(N_NODES + 1) * PAD];      // +1: zero row for gather padding
__device__ float d_bufB[(N_NODES + 1) * PAD];

// ---------------- fused: bucket scatter-fill (blocks 0..NB_E4) + x-projection (rest) ----------------
__global__ void __launch_bounds__(256)
k_fill_xproj(const int* __restrict__ ei, const float* __restrict__ x,
             const float* __restrict__ w) {
    __shared__ float ws[IN_CH * HID];
    __shared__ float xs[8][IN_CH];
    int tid = threadIdx.x;
    if (blockIdx.x < NB_E4) {
        int i = blockIdx.x * 256 + tid;
        int4 s4 = __ldg(&((const int4*)ei)[i]);
        int4 d4 = __ldg(&((const int4*)(ei + N_EDGES))[i]);
        int ss[4] = { s4.x, s4.y, s4.z, s4.w };
        int dd[4] = { d4.x, d4.y, d4.z, d4.w };
        #pragma unroll
        for (int j = 0; j < 4; j++) {
            int s = ss[j], d = dd[j];
            if ((unsigned)d < N_NODES && (unsigned)s < N_NODES) {
                int p = atomicAdd(&d_cnt[d], 1);
                if (p < BUCKET) d_bucket[d * BUCKET + p] = s;
            }
        }
    } else {
        int blk = blockIdx.x - NB_E4;
        int tx = tid & 31, ty = tid >> 5;
        for (int i = tid; i < IN_CH * HID; i += 256) ws[i] = w[i];
        int node0 = blk * 8;
        for (int i = tid; i < 8 * IN_CH; i += 256) {
            int r = i / IN_CH, c = i % IN_CH;
            xs[r][c] = x[(node0 + r) * IN_CH + c];
        }
        __syncthreads();
        int node = node0 + ty;
        float acc = 0.f;
        if (tx < HID) {
            #pragma unroll 16
            for (int k = 0; k < IN_CH; k++) acc += xs[ty][k] * ws[k * HID + tx];
        }
        d_bufA[node * PAD + tx] = (tx < HID) ? acc : 0.f;
    }
}

// ---------------- warp-per-node gather: lane = feature column ----------------
// returns h_lane = relu(self + sum_nb + biasA) for this lane's feature
__device__ __forceinline__ float gather_wpn(const float* __restrict__ in,
                                            float bav, int node, int lane) {
    int deg = min(__ldg(&d_cnt[node]), BUCKET);   // warp-uniform
    const int* colbase = d_bucket + node * BUCKET;
    float a0 = __ldg(&in[node * PAD + lane]);     // self term (coalesced 128B row)
    float a1 = 0.f, a2 = 0.f, a3 = 0.f;
    float a4 = 0.f, a5 = 0.f, a6 = 0.f, a7 = 0.f;
    for (int e = 0; e < deg; e += 32) {
        int rem = deg - e;
        int m = rem < 32 ? rem : 32;              // warp-uniform
        int c = __ldg(&colbase[e + lane]);        // 32 indices in one coalesced load
        #pragma unroll
        for (int jj = 0; jj < 4; jj++) {
            int j = jj * 8;
            if (j < m) {                          // warp-uniform branch
                // round tail up to 8 via zero-row reads: 8 independent loads in flight
                int s0 = (j + 0 < m) ? __shfl_sync(FULL, c, j + 0) : ZROW;
                int s1 = (j + 1 < m) ? __shfl_sync(FULL, c, j + 1) : ZROW;
                int s2 = (j + 2 < m) ? __shfl_sync(FULL, c, j + 2) : ZROW;
                int s3 = (j + 3 < m) ? __shfl_sync(FULL, c, j + 3) : ZROW;
                int s4 = (j + 4 < m) ? __shfl_sync(FULL, c, j + 4) : ZROW;
                int s5 = (j + 5 < m) ? __shfl_sync(FULL, c, j + 5) : ZROW;
                int s6 = (j + 6 < m) ? __shfl_sync(FULL, c, j + 6) : ZROW;
                int s7 = (j + 7 < m) ? __shfl_sync(FULL, c, j + 7) : ZROW;
                a0 += __ldg(&in[s0 * PAD + lane]);
                a1 += __ldg(&in[s1 * PAD + lane]);
                a2 += __ldg(&in[s2 * PAD + lane]);
                a3 += __ldg(&in[s3 * PAD + lane]);
                a4 += __ldg(&in[s4 * PAD + lane]);
                a5 += __ldg(&in[s5 * PAD + lane]);
                a6 += __ldg(&in[s6 * PAD + lane]);
                a7 += __ldg(&in[s7 * PAD + lane]);
            }
        }
    }
    float acc = ((a0 + a1) + (a2 + a3)) + ((a4 + a5) + (a6 + a7));
    return fmaxf(acc + bav, 0.f);                 // lanes >= HID: inputs 0, bav 0 -> h = 0
}

// ---------------- fused layer: gather -> relu(H@wb+bb) -> @wa_next -> outY ----------------
// No shared memory, no __syncthreads: weights live in registers, h broadcast by shuffle.
__global__ void __launch_bounds__(256)
k_layer(const float* __restrict__ in, float* __restrict__ outY,
        const float* __restrict__ biasA,
        const float* __restrict__ wb, const float* __restrict__ bb,
        const float* __restrict__ wa) {
    int lane = threadIdx.x & 31;
    int node = blockIdx.x * 8 + (threadIdx.x >> 5);
    float wbr[HID], war[HID];
    #pragma unroll
    for (int k = 0; k < HID; k++) {
        wbr[k] = (lane < HID) ? __ldg(&wb[k * HID + lane]) : 0.f;
        war[k] = (lane < HID) ? __ldg(&wa[k * HID + lane]) : 0.f;
    }
    float bbv = (lane < HID) ? __ldg(&bb[lane]) : 0.f;
    float bav = (lane < HID) ? __ldg(&biasA[lane]) : 0.f;

    float h = gather_wpn(in, bav, node, lane);

    float t = bbv;
    #pragma unroll
    for (int k = 0; k < HID; k++) t += __shfl_sync(FULL, h, k) * wbr[k];
    t = fmaxf(t, 0.f);                     // outer ReLU of the GIN layer
    float y = 0.f;
    #pragma unroll
    for (int k = 0; k < HID; k++) y += __shfl_sync(FULL, t, k) * war[k];
    outY[node * PAD + lane] = (lane < HID) ? y : 0.f;
}

// ---------------- final fused layer: gather -> relu(H@wb+bb) -> log_softmax -> out ----------------
__global__ void __launch_bounds__(256)
k_final(const float* __restrict__ in, float* __restrict__ out,
        const float* __restrict__ biasA,
        const float* __restrict__ wb, const float* __restrict__ bb) {
    int lane = threadIdx.x & 31;
    int node = blockIdx.x * 8 + (threadIdx.x >> 5);
    float wbr[HID];
    #pragma unroll
    for (int k = 0; k < HID; k++)
        wbr[k] = (lane < HID) ? __ldg(&wb[k * HID + lane]) : 0.f;
    float bbv = (lane < HID) ? __ldg(&bb[lane]) : 0.f;
    float bav = (lane < HID) ? __ldg(&biasA[lane]) : 0.f;

    float h = gather_wpn(in, bav, node, lane);

    float t = bbv;
    #pragma unroll
    for (int k = 0; k < HID; k++) t += __shfl_sync(FULL, h, k) * wbr[k];
    t = fmaxf(t, 0.f);

    float tv = (lane < HID) ? t : -1e30f;
    float m = tv;
    #pragma unroll
    for (int off = 16; off > 0; off >>= 1)
        m = fmaxf(m, __shfl_xor_sync(FULL, m, off));
    float ex = (lane < HID) ? __expf(tv - m) : 0.f;
    float s = ex;
    #pragma unroll
    for (int off = 16; off > 0; off >>= 1)
        s += __shfl_xor_sync(FULL, s, off);
    float lse = m + logf(s);
    if (lane < HID) out[node * HID + lane] = tv - lse;
}

// ---------------- launcher ----------------
extern "C" void kernel_launch(void* const* d_in, const int* in_sizes, int n_in,
                              void* d_out, int out_size) {
    const float* x   = (const float*)d_in[0];
    const int*   ei  = (const int*)d_in[1];   // int32 (JAX x64-disabled)
    const float* w1a = (const float*)d_in[2];
    const float* b1a = (const float*)d_in[3];
    const float* w1b = (const float*)d_in[4];
    const float* b1b = (const float*)d_in[5];
    const float* w2a = (const float*)d_in[6];
    const float* b2a = (const float*)d_in[7];
    const float* w2b = (const float*)d_in[8];
    const float* b2b = (const float*)d_in[9];
    const float* w3a = (const float*)d_in[10];
    const float* b3a = (const float*)d_in[11];
    const float* w3b = (const float*)d_in[12];
    const float* b3b = (const float*)d_in[13];
    float* out = (float*)d_out;

    void *p_cnt = 0, *p_A = 0, *p_B = 0;
    cudaGetSymbolAddress(&p_cnt, d_cnt);
    cudaGetSymbolAddress(&p_A, d_bufA);
    cudaGetSymbolAddress(&p_B, d_bufB);
    const float* Af = (const float*)p_A;
    const float* Bf = (const float*)p_B;

    // memsets = DMA nodes, not kernel launches
    cudaMemsetAsync(p_cnt, 0, N_NODES * sizeof(int));
    cudaMemsetAsync((char*)p_A + (size_t)ZROW * PAD * sizeof(float), 0, PAD * sizeof(float));
    cudaMemsetAsync((char*)p_B + (size_t)ZROW * PAD * sizeof(float), 0, PAD * sizeof(float));

    // kernel 0: single-pass bucket fill (edge blocks) + xproj (node blocks)
    k_fill_xproj<<<NB_E4 + NB_XPROJ, 256>>>(ei, x, w1a);
    // kernel 1: layer 1
    k_layer<<<N_NODES / 8, 256>>>(Af, (float*)p_B, b1a, w1b, b1b, w2a);
    // kernel 2: layer 2
    k_layer<<<N_NODES / 8, 256>>>(Bf, (float*)p_A, b2a, w2b, b2b, w3a);
    // kernel 3: layer 3 + log_softmax  <-- profiled slot
    k_final<<<N_NODES / 8, 256>>>(Af, out, b3a, w3b, b3b);
}

// round 8
// speedup vs baseline: 2.0161x; 2.0161x over previous
#include <cuda_runtime.h>
#include <math.h>

#define N_NODES 100000
#define N_EDGES 3200000
#define IN_CH   128
#define HID     30
#define PAD     32
#define BUCKET  128            // max degree capacity (Poisson(32): overflow prob ~0)
#define NB_E4   3125           // (N_EDGES/4)/256
#define NB_XPROJ 12500         // N_NODES/8

// ---- scratch (static device globals; no allocation anywhere) ----
__device__ int   d_cnt[N_NODES];
__device__ int   d_bucket[N_NODES * BUCKET];   // 51.2 MB
__device__ float d_bufA[N_NODES * PAD];
__device__ float d_bufB[N_NODES * PAD];

// ---------------- fused: bucket scatter-fill (blocks 0..NB_E4) + x-projection (rest) ----------------
__global__ void __launch_bounds__(256)
k_fill_xproj(const int* __restrict__ ei, const float* __restrict__ x,
             const float* __restrict__ w) {
    __shared__ float ws[IN_CH * HID];
    __shared__ float xs[8][IN_CH];
    int tid = threadIdx.x;
    if (blockIdx.x < NB_E4) {
        int i = blockIdx.x * 256 + tid;
        int4 s4 = __ldg(&((const int4*)ei)[i]);
        int4 d4 = __ldg(&((const int4*)(ei + N_EDGES))[i]);
        int ss[4] = { s4.x, s4.y, s4.z, s4.w };
        int dd[4] = { d4.x, d4.y, d4.z, d4.w };
        #pragma unroll
        for (int j = 0; j < 4; j++) {
            int s = ss[j], d = dd[j];
            if ((unsigned)d < N_NODES && (unsigned)s < N_NODES) {
                int p = atomicAdd(&d_cnt[d], 1);
                if (p < BUCKET) d_bucket[d * BUCKET + p] = s;
            }
        }
    } else {
        int blk = blockIdx.x - NB_E4;
        int tx = tid & 31, ty = tid >> 5;
        for (int i = tid; i < IN_CH * HID; i += 256) ws[i] = w[i];
        int node0 = blk * 8;
        for (int i = tid; i < 8 * IN_CH; i += 256) {
            int r = i / IN_CH, c = i % IN_CH;
            xs[r][c] = x[(node0 + r) * IN_CH + c];
        }
        __syncthreads();
        int node = node0 + ty;
        float acc = 0.f;
        if (tx < HID) {
            #pragma unroll 16
            for (int k = 0; k < IN_CH; k++) acc += xs[ty][k] * ws[k * HID + tx];
        }
        d_bufA[node * PAD + tx] = (tx < HID) ? acc : 0.f;
    }
}

// ---------------- gather (Round-6 form): 8 lanes/node, float4, shuffle-broadcast cols ----------------
__device__ __forceinline__ void gather_phase(const float4* __restrict__ in,
                                             const float* __restrict__ biasA,
                                             float sh_h[32][32], int tid, int blk) {
    int g    = tid >> 3;
    int lane = tid & 7;
    int gw   = g & 3;
    unsigned gmask = 0xFFu << (gw * 8);
    int node = blk * 32 + g;
    int deg  = min(__ldg(&d_cnt[node]), BUCKET);
    const int* colbase = d_bucket + node * BUCKET;

    float4 acc = __ldg(&in[node * 8 + lane]);   // self term
    float4 acc2 = make_float4(0.f, 0.f, 0.f, 0.f);
    int e = 0;
    for (; e + 8 <= deg; e += 8) {
        int c = __ldg(&colbase[e + lane]);      // 8 consecutive ints per group (1 sector)
        int s0 = __shfl_sync(gmask, c, gw * 8 + 0);
        int s1 = __shfl_sync(gmask, c, gw * 8 + 1);
        int s2 = __shfl_sync(gmask, c, gw * 8 + 2);
        int s3 = __shfl_sync(gmask, c, gw * 8 + 3);
        int s4 = __shfl_sync(gmask, c, gw * 8 + 4);
        int s5 = __shfl_sync(gmask, c, gw * 8 + 5);
        int s6 = __shfl_sync(gmask, c, gw * 8 + 6);
        int s7 = __shfl_sync(gmask, c, gw * 8 + 7);
        float4 v0 = __ldg(&in[s0 * 8 + lane]);
        float4 v1 = __ldg(&in[s1 * 8 + lane]);
        float4 v2 = __ldg(&in[s2 * 8 + lane]);
        float4 v3 = __ldg(&in[s3 * 8 + lane]);
        float4 v4 = __ldg(&in[s4 * 8 + lane]);
        float4 v5 = __ldg(&in[s5 * 8 + lane]);
        float4 v6 = __ldg(&in[s6 * 8 + lane]);
        float4 v7 = __ldg(&in[s7 * 8 + lane]);
        acc.x  += v0.x + v1.x + v2.x + v3.x;
        acc.y  += v0.y + v1.y + v2.y + v3.y;
        acc.z  += v0.z + v1.z + v2.z + v3.z;
        acc.w  += v0.w + v1.w + v2.w + v3.w;
        acc2.x += v4.x + v5.x + v6.x + v7.x;
        acc2.y += v4.y + v5.y + v6.y + v7.y;
        acc2.z += v4.z + v5.z + v6.z + v7.z;
        acc2.w += v4.w + v5.w + v6.w + v7.w;
    }
    for (; e < deg; e++) {
        int s = __ldg(&colbase[e]);
        float4 v = __ldg(&in[s * 8 + lane]);
        acc.x += v.x; acc.y += v.y; acc.z += v.z; acc.w += v.w;
    }
    acc.x += acc2.x; acc.y += acc2.y; acc.z += acc2.z; acc.w += acc2.w;
    int c4 = lane * 4;
    float4 b;
    b.x = (c4 + 0 < HID) ? __ldg(&biasA[c4 + 0]) : 0.f;
    b.y = (c4 + 1 < HID) ? __ldg(&biasA[c4 + 1]) : 0.f;
    b.z = (c4 + 2 < HID) ? __ldg(&biasA[c4 + 2]) : 0.f;
    b.w = (c4 + 3 < HID) ? __ldg(&biasA[c4 + 3]) : 0.f;
    float4 o;
    o.x = fmaxf(acc.x + b.x, 0.f);
    o.y = fmaxf(acc.y + b.y, 0.f);
    o.z = fmaxf(acc.z + b.z, 0.f);
    o.w = fmaxf(acc.w + b.w, 0.f);
    *(float4*)&sh_h[g][lane * 4] = o;       // cols >= HID are exactly 0
}

// ---- register-cached weight column for one output feature tx ----
// sh_src rows have cols 30,31 == 0, so garbage wcol[30],wcol[31] contribute 0.
__device__ __forceinline__ float mlp_dot(const float sh_row[32], const float wcol[32]) {
    const float4* h4 = (const float4*)sh_row;   // broadcast LDS.128, conflict-free
    float a = 0.f;
    #pragma unroll
    for (int q = 0; q < 8; q++) {
        float4 hv = h4[q];
        a += hv.x * wcol[q * 4 + 0] + hv.y * wcol[q * 4 + 1]
           + hv.z * wcol[q * 4 + 2] + hv.w * wcol[q * 4 + 3];
    }
    return a;
}

// ---------------- fused layer: gather -> relu(H@wb+bb) -> @wa_next -> outY ----------------
__global__ void __launch_bounds__(256)
k_layer(const float4* __restrict__ in, float* __restrict__ outY,
        const float* __restrict__ biasA,
        const float* __restrict__ wb, const float* __restrict__ bb,
        const float* __restrict__ wa) {
    __shared__ float sh_h[32][32];
    __shared__ float sh_t[32][32];
    __shared__ float wbs[HID * HID], was[HID * HID], bbs[32];
    int tid = threadIdx.x;
    for (int i = tid; i < HID * HID; i += 256) { wbs[i] = wb[i]; was[i] = wa[i]; }
    if (tid < 32) bbs[tid] = (tid < HID) ? bb[tid] : 0.f;

    gather_phase(in, biasA, sh_h, tid, blockIdx.x);
    __syncthreads();

    int tx = tid & 31, ty = tid >> 5;
    float wcol[32];
    #pragma unroll
    for (int k = 0; k < HID; k++) wcol[k] = (tx < HID) ? wbs[k * HID + tx] : 0.f;
    wcol[30] = 0.f; wcol[31] = 0.f;
    #pragma unroll
    for (int p = 0; p < 4; p++) {
        int n = p * 8 + ty;
        float a = fmaxf(bbs[tx] + mlp_dot(sh_h[n], wcol), 0.f);  // outer ReLU
        sh_t[n][tx] = (tx < HID) ? a : 0.f;
    }
    __syncthreads();
    #pragma unroll
    for (int k = 0; k < HID; k++) wcol[k] = (tx < HID) ? was[k * HID + tx] : 0.f;
    #pragma unroll
    for (int p = 0; p < 4; p++) {
        int n = p * 8 + ty;
        float a = mlp_dot(sh_t[n], wcol);
        outY[(blockIdx.x * 32 + n) * PAD + tx] = (tx < HID) ? a : 0.f;
    }
}

// ---------------- final fused layer: gather -> relu(H@wb+bb) -> log_softmax -> out ----------------
__global__ void __launch_bounds__(256)
k_final(const float4* __restrict__ in, float* __restrict__ out,
        const float* __restrict__ biasA,
        const float* __restrict__ wb, const float* __restrict__ bb) {
    __shared__ float sh_h[32][32];
    __shared__ float wbs[HID * HID], bbs[32];
    int tid = threadIdx.x;
    for (int i = tid; i < HID * HID; i += 256) wbs[i] = wb[i];
    if (tid < 32) bbs[tid] = (tid < HID) ? bb[tid] : 0.f;

    gather_phase(in, biasA, sh_h, tid, blockIdx.x);
    __syncthreads();

    int tx = tid & 31, ty = tid >> 5;
    float wcol[32];
    #pragma unroll
    for (int k = 0; k < HID; k++) wcol[k] = (tx < HID) ? wbs[k * HID + tx] : 0.f;
    wcol[30] = 0.f; wcol[31] = 0.f;
    #pragma unroll
    for (int p = 0; p < 4; p++) {
        int n = p * 8 + ty;
        float t = fmaxf(bbs[tx] + mlp_dot(sh_h[n], wcol), 0.f);
        float tv = (tx < HID) ? t : -1e30f;
        float m = tv;
        #pragma unroll
        for (int off = 16; off > 0; off >>= 1)
            m = fmaxf(m, __shfl_xor_sync(0xffffffff, m, off));
        float ex = (tx < HID) ? __expf(tv - m) : 0.f;
        float s = ex;
        #pragma unroll
        for (int off = 16; off > 0; off >>= 1)
            s += __shfl_xor_sync(0xffffffff, s, off);
        float lse = m + logf(s);
        if (tx < HID) out[(blockIdx.x * 32 + n) * HID + tx] = tv - lse;
    }
}

// ---------------- launcher ----------------
extern "C" void kernel_launch(void* const* d_in, const int* in_sizes, int n_in,
                              void* d_out, int out_size) {
    const float* x   = (const float*)d_in[0];
    const int*   ei  = (const int*)d_in[1];   // int32 (JAX x64-disabled)
    const float* w1a = (const float*)d_in[2];
    const float* b1a = (const float*)d_in[3];
    const float* w1b = (const float*)d_in[4];
    const float* b1b = (const float*)d_in[5];
    const float* w2a = (const float*)d_in[6];
    const float* b2a = (const float*)d_in[7];
    const float* w2b = (const float*)d_in[8];
    const float* b2b = (const float*)d_in[9];
    const float* w3a = (const float*)d_in[10];
    const float* b3a = (const float*)d_in[11];
    const float* w3b = (const float*)d_in[12];
    const float* b3b = (const float*)d_in[13];
    float* out = (float*)d_out;

    void *p_cnt = 0, *p_A = 0, *p_B = 0;
    cudaGetSymbolAddress(&p_cnt, d_cnt);
    cudaGetSymbolAddress(&p_A, d_bufA);
    cudaGetSymbolAddress(&p_B, d_bufB);
    const float4* A4 = (const float4*)p_A;
    const float4* B4 = (const float4*)p_B;

    // memset = DMA node, not a kernel launch
    cudaMemsetAsync(p_cnt, 0, N_NODES * sizeof(int));

    // kernel 0: single-pass bucket fill (edge blocks) + xproj (node blocks)
    k_fill_xproj<<<NB_E4 + NB_XPROJ, 256>>>(ei, x, w1a);
    // kernel 1: layer 1
    k_layer<<<N_NODES / 32, 256>>>(A4, (float*)p_B, b1a, w1b, b1b, w2a);
    // kernel 2: layer 2
    k_layer<<<N_NODES / 32, 256>>>(B4, (float*)p_A, b2a, w2b, b2b, w3a);
    // kernel 3: layer 3 + log_softmax  <-- profiled slot
    k_final<<<N_NODES / 32, 256>>>(A4, out, b3a, w3b, b3b);
}